// round 4
// baseline (speedup 1.0000x reference)
#include <cuda_runtime.h>
#include <cstdint>

typedef unsigned long long u64;

// ---------------- f32x2 packed helpers (sm_103a) ----------------
__device__ __forceinline__ u64 pack2(float x, float y) {
    u64 r; asm("mov.b64 %0, {%1,%2};" : "=l"(r) : "f"(x), "f"(y)); return r;
}
__device__ __forceinline__ void unpack2(u64 v, float& x, float& y) {
    asm("mov.b64 {%0,%1}, %2;" : "=f"(x), "=f"(y) : "l"(v));
}
__device__ __forceinline__ u64 fma2(u64 a, u64 b, u64 c) {
    u64 d; asm("fma.rn.f32x2 %0,%1,%2,%3;" : "=l"(d) : "l"(a), "l"(b), "l"(c)); return d;
}
__device__ __forceinline__ u64 mul2(u64 a, u64 b) {
    u64 d; asm("mul.rn.f32x2 %0,%1,%2;" : "=l"(d) : "l"(a), "l"(b)); return d;
}
__device__ __forceinline__ u64 add2(u64 a, u64 b) {
    u64 d; asm("add.rn.f32x2 %0,%1,%2;" : "=l"(d) : "l"(a), "l"(b)); return d;
}

// Problem constants (fixed by the reference: B=4, C=64, H=W=256, K=7)
#define HH 256
#define WW 256
#define CC 64
#define PAD 3
#define TILE_W 64
#define TILE_H 16
#define HALO_W (TILE_W + 2 * PAD)   // 70
#define HALO_H (TILE_H + 2 * PAD)   // 22
#define SROW 120                     // float2 stride per row; 120 % 16 == 8 -> 2-phase LDS.64
#define NTHREADS 128
#define CH_PER_BLOCK 16              // 8 channel-pair iterations per block

__global__ void __launch_bounds__(NTHREADS, 3)
gauss_smooth_kernel(const float* __restrict__ x,
                    const float* __restrict__ persp,
                    const float* __restrict__ alpha,
                    const float* __restrict__ beta,
                    const float* __restrict__ gamma,
                    float* __restrict__ out)
{
    // Strip-major duplicated tile: tile[r*SROW + m*8 + k] holds halo column
    // c = 8k+m, for strip m in 0..13, k in 0..7 (interior columns stored twice).
    __shared__ u64 tile[HALO_H * SROW];

    const int tid = threadIdx.x;
    const int tx  = tid & 7;         // column-strip index (8 output cols each)
    const int ty  = tid >> 3;        // output row within tile (0..15)

    const int b   = blockIdx.z >> 2;
    const int cg  = blockIdx.z & 3;
    const int c0  = cg * CH_PER_BLOCK;
    const int gx0 = blockIdx.x * TILE_W;
    const int gy0 = blockIdx.y * TILE_H;

    const int oy  = gy0 + ty;        // output row (global)
    const int ocx = gx0 + tx * 8;    // first output col (global)

    // ---------------- per-pixel weights (shared across all channels) ----------
    const float al = alpha[0];
    const float be = beta[0];
    const float ga = gamma[0];

    u64 W2[8][4];                    // broadcast-packed normalized weights by tap distance
    {
        const float* prow = persp + ((size_t)b * HH * WW) + oy * WW + ocx;
        #pragma unroll
        for (int px = 0; px < 8; ++px) {
            float p  = prow[px];
            float z  = fmaf(be, p, ga);
            float sg = __fdividef(1.0f, 1.0f + __expf(-z));
            float sig = fmaxf(al * sg, 1e-4f);
            float u  = __fdividef(0.5f, sig * sig);
            float t1 = __expf(-u);
            float t4 = t1 * t1; t4 = t4 * t4;          // t^4
            float t9 = t4 * t4 * t1;                    // t^9
            float S  = 1.0f + 2.0f * (t1 + t4 + t9);
            float inv = __fdividef(1.0f, S);
            float w0 = inv, w1 = t1 * inv, w2 = t4 * inv, w3 = t9 * inv;
            W2[px][0] = pack2(w0, w0);
            W2[px][1] = pack2(w1, w1);
            W2[px][2] = pack2(w2, w2);
            W2[px][3] = pack2(w3, w3);
        }
    }

    const int sbase = ty * SROW + tx;

    // ---------------- channel-pair loop ----------------
    #pragma unroll 1
    for (int cp = 0; cp < CH_PER_BLOCK / 2; ++cp) {
        const int c = c0 + 2 * cp;
        const float* xa = x + (((size_t)(b * CC + c)) << 16);
        const float* xb = xa + (HH * WW);

        // Load halo tile (2 channels interleaved), duplicated strip-major layout.
        #pragma unroll 1
        for (int idx = tid; idx < HALO_H * HALO_W; idx += NTHREADS) {
            int r  = idx / HALO_W;
            int cc = idx - r * HALO_W;
            int gy = gy0 - PAD + r;
            int gx = gx0 - PAD + cc;
            float va = 0.0f, vb = 0.0f;
            if ((unsigned)gy < (unsigned)HH && (unsigned)gx < (unsigned)WW) {
                int o = (gy << 8) + gx;
                va = xa[o];
                vb = xb[o];
            }
            u64 v = pack2(va, vb);
            int m  = cc & 7;
            int k  = cc >> 3;
            int rb = r * SROW;
            // slot (m, k): strips 0..7   (valid when cc < 64)
            if (cc < 64) tile[rb + m * 8 + k] = v;
            // slot (m+8, k-1): strips 8..13 (valid when m+8 <= 13 and k >= 1)
            if (cc >= 8 && m < 6) tile[rb + (m + 8) * 8 + (k - 1)] = v;
        }
        __syncthreads();

        // Compute: vertical symmetry fold (rows +/-d share weight), then
        // horizontal 7-tap with symmetric weights, all in packed f32x2.
        u64 acc[8];
        #pragma unroll
        for (int px = 0; px < 8; ++px) acc[px] = 0ull;

        #pragma unroll
        for (int d = 0; d < 4; ++d) {
            u64 g[14];
            if (d < 3) {
                const u64* ra = &tile[sbase + d * SROW];
                const u64* rb = &tile[sbase + (6 - d) * SROW];
                #pragma unroll
                for (int m = 0; m < 14; ++m) g[m] = add2(ra[m * 8], rb[m * 8]);
            } else {
                const u64* rc = &tile[sbase + 3 * SROW];
                #pragma unroll
                for (int m = 0; m < 14; ++m) g[m] = rc[m * 8];
            }
            const int vk = (d < 3) ? (3 - d) : 0;  // vertical tap distance weight idx
            #pragma unroll
            for (int px = 0; px < 8; ++px) {
                u64 h = mul2(W2[px][3], g[px]);
                h = fma2(W2[px][2], g[px + 1], h);
                h = fma2(W2[px][1], g[px + 2], h);
                h = fma2(W2[px][0], g[px + 3], h);
                h = fma2(W2[px][1], g[px + 4], h);
                h = fma2(W2[px][2], g[px + 5], h);
                h = fma2(W2[px][3], g[px + 6], h);
                acc[px] = fma2(W2[px][vk], h, acc[px]);
            }
        }

        // Write out: channel c (.x lanes) and c+1 (.y lanes), vectorized.
        float ax[8], ay[8];
        #pragma unroll
        for (int px = 0; px < 8; ++px) unpack2(acc[px], ax[px], ay[px]);

        float* ob = out + (((size_t)(b * CC + c)) << 16) + (oy << 8) + ocx;
        *reinterpret_cast<float4*>(ob)     = make_float4(ax[0], ax[1], ax[2], ax[3]);
        *reinterpret_cast<float4*>(ob + 4) = make_float4(ax[4], ax[5], ax[6], ax[7]);
        float* ob2 = ob + (HH * WW);
        *reinterpret_cast<float4*>(ob2)     = make_float4(ay[0], ay[1], ay[2], ay[3]);
        *reinterpret_cast<float4*>(ob2 + 4) = make_float4(ay[4], ay[5], ay[6], ay[7]);

        __syncthreads();   // protect tile reuse in next iteration
    }
}

extern "C" void kernel_launch(void* const* d_in, const int* in_sizes, int n_in,
                              void* d_out, int out_size)
{
    const float* x     = (const float*)d_in[0];
    const float* persp = (const float*)d_in[1];
    const float* alpha = (const float*)d_in[2];
    const float* beta  = (const float*)d_in[3];
    const float* gamma = (const float*)d_in[4];
    float* out = (float*)d_out;

    dim3 grid(WW / TILE_W, HH / TILE_H, 4 * (CC / CH_PER_BLOCK)); // (4, 16, 16)
    dim3 block(NTHREADS);
    gauss_smooth_kernel<<<grid, block>>>(x, persp, alpha, beta, gamma, out);
}

// round 5
// speedup vs baseline: 1.0309x; 1.0309x over previous
#include <cuda_runtime.h>
#include <cstdint>

typedef unsigned long long u64;

// ---------------- f32x2 packed helpers (sm_103a) ----------------
__device__ __forceinline__ u64 pack2(float x, float y) {
    u64 r; asm("mov.b64 %0, {%1,%2};" : "=l"(r) : "f"(x), "f"(y)); return r;
}
__device__ __forceinline__ void unpack2(u64 v, float& x, float& y) {
    asm("mov.b64 {%0,%1}, %2;" : "=f"(x), "=f"(y) : "l"(v));
}
__device__ __forceinline__ u64 fma2(u64 a, u64 b, u64 c) {
    u64 d; asm("fma.rn.f32x2 %0,%1,%2,%3;" : "=l"(d) : "l"(a), "l"(b), "l"(c)); return d;
}
__device__ __forceinline__ u64 mul2(u64 a, u64 b) {
    u64 d; asm("mul.rn.f32x2 %0,%1,%2;" : "=l"(d) : "l"(a), "l"(b)); return d;
}
__device__ __forceinline__ u64 add2(u64 a, u64 b) {
    u64 d; asm("add.rn.f32x2 %0,%1,%2;" : "=l"(d) : "l"(a), "l"(b)); return d;
}

// Problem constants (fixed by the reference: B=4, C=64, H=W=256, K=7)
#define HH 256
#define WW 256
#define CC 64
#define PAD 3
#define TILE_W 64
#define TILE_H 16
#define HALO_W (TILE_W + 2 * PAD)   // 70
#define HALO_H (TILE_H + 2 * PAD)   // 22
#define HALO_N (HALO_H * HALO_W)    // 1540
#define SROW 120                     // u64 stride per row; 120 % 16 == 8 -> 2-phase LDS.64
#define TILE_SZ (HALO_H * SROW)      // 2640 u64 = 21.1 KB
#define NTHREADS 128
#define CH_PER_BLOCK 16              // 8 channel-pair iterations per block
#define LOAD_TRIPS 13                // ceil(1540 / 128)

// Load one channel-pair halo tile into the given smem buffer.
// Division-free indexing: element idx = tid + 128*e; (r, cc) advanced by
// (+1, +58) mod-70 carry per trip.
__device__ __forceinline__ void load_tile(u64* __restrict__ buf,
                                          const float* __restrict__ xa,
                                          const float* __restrict__ xb,
                                          int gx0, int gy0, int tid)
{
    int r = 0, cc = tid;
    if (cc >= HALO_W) { cc -= HALO_W; r = 1; }   // tid < 140 always → at most one carry
    #pragma unroll
    for (int e = 0; e < LOAD_TRIPS; ++e) {
        if (r < HALO_H) {
            int gy = gy0 - PAD + r;
            int gx = gx0 - PAD + cc;
            float va = 0.0f, vb = 0.0f;
            if ((unsigned)gy < (unsigned)HH && (unsigned)gx < (unsigned)WW) {
                int o = (gy << 8) + gx;
                va = xa[o];
                vb = xb[o];
            }
            u64 v = pack2(va, vb);
            int m  = cc & 7;
            int k  = cc >> 3;
            int rb = r * SROW;
            // slot (m, k): strips 0..7   (valid when cc < 64)
            if (cc < 64) buf[rb + m * 8 + k] = v;
            // slot (m+8, k-1): strips 8..13 (valid when m <= 5 and k >= 1)
            if (cc >= 8 && m < 6) buf[rb + (m + 8) * 8 + (k - 1)] = v;
        }
        // advance by 128 = 70 + 58
        r += 1; cc += 58;
        if (cc >= HALO_W) { cc -= HALO_W; ++r; }
    }
}

__global__ void __launch_bounds__(NTHREADS, 4)
gauss_smooth_kernel(const float* __restrict__ x,
                    const float* __restrict__ persp,
                    const float* __restrict__ alpha,
                    const float* __restrict__ beta,
                    const float* __restrict__ gamma,
                    float* __restrict__ out)
{
    // Double-buffered strip-major duplicated tile:
    // tile[b][r*SROW + m*8 + k] holds halo column c = 8k+m (m in 0..13, k in 0..7).
    __shared__ u64 tile[2][TILE_SZ];

    const int tid = threadIdx.x;
    const int tx  = tid & 7;         // column-strip index (8 output cols each)
    const int ty  = tid >> 3;        // output row within tile (0..15)

    const int b   = blockIdx.z >> 2;
    const int cg  = blockIdx.z & 3;
    const int c0  = cg * CH_PER_BLOCK;
    const int gx0 = blockIdx.x * TILE_W;
    const int gy0 = blockIdx.y * TILE_H;

    const int oy  = gy0 + ty;        // output row (global)
    const int ocx = gx0 + tx * 8;    // first output col (global)

    // ---------------- per-pixel weights (shared across all channels) ----------
    const float al = alpha[0];
    const float be = beta[0];
    const float ga = gamma[0];

    u64 W2[8][4];                    // broadcast-packed normalized weights by tap distance
    {
        const float* prow = persp + ((size_t)b * HH * WW) + oy * WW + ocx;
        #pragma unroll
        for (int px = 0; px < 8; ++px) {
            float p  = prow[px];
            float z  = fmaf(be, p, ga);
            float sg = __fdividef(1.0f, 1.0f + __expf(-z));
            float sig = fmaxf(al * sg, 1e-4f);
            float u  = __fdividef(0.5f, sig * sig);
            float t1 = __expf(-u);
            float t4 = t1 * t1; t4 = t4 * t4;          // t^4
            float t9 = t4 * t4 * t1;                    // t^9
            float S  = 1.0f + 2.0f * (t1 + t4 + t9);
            float inv = __fdividef(1.0f, S);
            float w0 = inv, w1 = t1 * inv, w2 = t4 * inv, w3 = t9 * inv;
            W2[px][0] = pack2(w0, w0);
            W2[px][1] = pack2(w1, w1);
            W2[px][2] = pack2(w2, w2);
            W2[px][3] = pack2(w3, w3);
        }
    }

    const int sbase = ty * SROW + tx;
    const size_t plane = (size_t)HH * WW;
    const float* xbase = x + ((size_t)(b * CC + c0)) * plane;

    // Prologue: load first channel-pair tile into buffer 0.
    load_tile(tile[0], xbase, xbase + plane, gx0, gy0, tid);
    __syncthreads();

    // ---------------- channel-pair loop (double-buffered) ----------------
    #pragma unroll 1
    for (int cp = 0; cp < CH_PER_BLOCK / 2; ++cp) {
        const u64* cur = tile[cp & 1];

        // Prefetch next channel pair into the other buffer (overlaps compute).
        if (cp < CH_PER_BLOCK / 2 - 1) {
            const float* xa = xbase + (size_t)(2 * cp + 2) * plane;
            load_tile(tile[(cp & 1) ^ 1], xa, xa + plane, gx0, gy0, tid);
        }

        // Compute: vertical symmetry fold (rows +/-d share weight), then
        // horizontal 7-tap with symmetric weights, all in packed f32x2.
        u64 acc[8];
        #pragma unroll
        for (int px = 0; px < 8; ++px) acc[px] = 0ull;

        #pragma unroll
        for (int d = 0; d < 4; ++d) {
            u64 g[14];
            if (d < 3) {
                const u64* ra = &cur[sbase + d * SROW];
                const u64* rb = &cur[sbase + (6 - d) * SROW];
                #pragma unroll
                for (int m = 0; m < 14; ++m) g[m] = add2(ra[m * 8], rb[m * 8]);
            } else {
                const u64* rc = &cur[sbase + 3 * SROW];
                #pragma unroll
                for (int m = 0; m < 14; ++m) g[m] = rc[m * 8];
            }
            const int vk = (d < 3) ? (3 - d) : 0;  // vertical tap distance weight idx
            #pragma unroll
            for (int px = 0; px < 8; ++px) {
                u64 h = mul2(W2[px][3], g[px]);
                h = fma2(W2[px][2], g[px + 1], h);
                h = fma2(W2[px][1], g[px + 2], h);
                h = fma2(W2[px][0], g[px + 3], h);
                h = fma2(W2[px][1], g[px + 4], h);
                h = fma2(W2[px][2], g[px + 5], h);
                h = fma2(W2[px][3], g[px + 6], h);
                acc[px] = fma2(W2[px][vk], h, acc[px]);
            }
        }

        // Write out: channel c (.x lanes) and c+1 (.y lanes), vectorized.
        float ax[8], ay[8];
        #pragma unroll
        for (int px = 0; px < 8; ++px) unpack2(acc[px], ax[px], ay[px]);

        const int c = c0 + 2 * cp;
        float* ob = out + ((size_t)(b * CC + c)) * plane + (oy << 8) + ocx;
        *reinterpret_cast<float4*>(ob)     = make_float4(ax[0], ax[1], ax[2], ax[3]);
        *reinterpret_cast<float4*>(ob + 4) = make_float4(ax[4], ax[5], ax[6], ax[7]);
        float* ob2 = ob + plane;
        *reinterpret_cast<float4*>(ob2)     = make_float4(ay[0], ay[1], ay[2], ay[3]);
        *reinterpret_cast<float4*>(ob2 + 4) = make_float4(ay[4], ay[5], ay[6], ay[7]);

        __syncthreads();   // next-buffer writes complete; current buffer free for reuse
    }
}

extern "C" void kernel_launch(void* const* d_in, const int* in_sizes, int n_in,
                              void* d_out, int out_size)
{
    const float* x     = (const float*)d_in[0];
    const float* persp = (const float*)d_in[1];
    const float* alpha = (const float*)d_in[2];
    const float* beta  = (const float*)d_in[3];
    const float* gamma = (const float*)d_in[4];
    float* out = (float*)d_out;

    dim3 grid(WW / TILE_W, HH / TILE_H, 4 * (CC / CH_PER_BLOCK)); // (4, 16, 16)
    dim3 block(NTHREADS);
    gauss_smooth_kernel<<<grid, block>>>(x, persp, alpha, beta, gamma, out);
}

// round 6
// speedup vs baseline: 2.1175x; 2.0540x over previous
#include <cuda_runtime.h>
#include <cstdint>

typedef unsigned long long u64;

// ---------------- f32x2 packed helpers (sm_103a) ----------------
__device__ __forceinline__ u64 pack2(float x, float y) {
    u64 r; asm("mov.b64 %0, {%1,%2};" : "=l"(r) : "f"(x), "f"(y)); return r;
}
__device__ __forceinline__ void unpack2(u64 v, float& x, float& y) {
    asm("mov.b64 {%0,%1}, %2;" : "=f"(x), "=f"(y) : "l"(v));
}
__device__ __forceinline__ u64 fma2(u64 a, u64 b, u64 c) {
    u64 d; asm("fma.rn.f32x2 %0,%1,%2,%3;" : "=l"(d) : "l"(a), "l"(b), "l"(c)); return d;
}
__device__ __forceinline__ u64 mul2(u64 a, u64 b) {
    u64 d; asm("mul.rn.f32x2 %0,%1,%2;" : "=l"(d) : "l"(a), "l"(b)); return d;
}
__device__ __forceinline__ u64 add2(u64 a, u64 b) {
    u64 d; asm("add.rn.f32x2 %0,%1,%2;" : "=l"(d) : "l"(a), "l"(b)); return d;
}

// Problem constants (B=4, C=64, H=W=256, K=7)
#define HH 256
#define WW 256
#define CC 64
#define PAD 3
#define TILE_W 32
#define TILE_H 16
#define HALO_W 38                    // TILE_W + 6
#define HALO_H 22                    // TILE_H + 6
#define SROW 88                      // u64 per tile row (80 slots + 8 pad); 88%16==8 -> conflict-free
#define TILE_SZ (HALO_H * SROW)      // 1936 u64 = 15.5 KB
#define NTHREADS 128
#define CH_PER_BLOCK 16              // 8 channel-pair iterations per block
#define F4_PER_ROW 10                // float4 windows covering [gx0-4, gx0+36)
#define NPAIRS (F4_PER_ROW * HALO_H) // 220 float4-pairs per tile

__device__ __forceinline__ float4 ldg_f4_guard(const float* p, bool pred) {
    float4 v = make_float4(0.f, 0.f, 0.f, 0.f);
    if (pred) v = *reinterpret_cast<const float4*>(p);
    return v;
}

// Issue the (predicated) global loads for one channel-pair tile into registers.
// No dependent instruction follows -> LDG latency overlaps with caller's compute.
__device__ __forceinline__ void tile_ldg(const float* __restrict__ xa,
                                         int gx0, int gy0, int tid,
                                         float4 fa[2], float4 fb[2])
{
    #pragma unroll
    for (int e = 0; e < 2; ++e) {
        int j = tid + NTHREADS * e;
        bool valid = (j < NPAIRS);
        int row = j / F4_PER_ROW;                 // constant div (mul-high)
        int c4  = j - row * F4_PER_ROW;
        int gy  = gy0 - PAD + row;
        int gxs = gx0 - 4 + 4 * c4;               // float4-aligned start
        bool inb = valid && ((unsigned)gy < (unsigned)HH) && ((unsigned)gxs < (unsigned)WW);
        const float* pa = xa + (gy << 8) + gxs;
        fa[e] = ldg_f4_guard(pa, inb);
        fb[e] = ldg_f4_guard(pa + HH * WW, inb);
    }
}

// Scatter the register-held tile into the duplicated strip-major smem layout.
// Slot (m, k) holds halo column c = 4k + m (strip m in 0..9, k in 0..7);
// interior columns are stored up to 3x so compute reads are conflict-free.
__device__ __forceinline__ void tile_sts(u64* __restrict__ buf, int tid,
                                         const float4 fa[2], const float4 fb[2])
{
    #pragma unroll
    for (int e = 0; e < 2; ++e) {
        int j = tid + NTHREADS * e;
        if (j < NPAIRS) {
            int row = j / F4_PER_ROW;
            int c4  = j - row * F4_PER_ROW;
            int rb  = row * SROW;
            int lc0 = 4 * c4 - 1;                 // halo col of lane i=0
            float va[4] = {fa[e].x, fa[e].y, fa[e].z, fa[e].w};
            float vb[4] = {fb[e].x, fb[e].y, fb[e].z, fb[e].w};
            #pragma unroll
            for (int i = 0; i < 4; ++i) {
                int lc = lc0 + i;
                if ((unsigned)lc < (unsigned)HALO_W) {
                    u64 v = pack2(va[i], vb[i]);
                    int q  = lc >> 2;
                    int mr = lc & 3;
                    if (lc < 32)               buf[rb + mr * 8 + q]           = v; // m=mr,   k=q
                    if (lc >= 4 && lc < 36)    buf[rb + (mr + 4) * 8 + q - 1] = v; // m=mr+4, k=q-1
                    if (lc >= 8 && mr < 2)     buf[rb + (mr + 8) * 8 + q - 2] = v; // m=mr+8, k=q-2
                }
            }
        }
    }
}

__global__ void __launch_bounds__(NTHREADS, 5)
gauss_smooth_kernel(const float* __restrict__ x,
                    const float* __restrict__ persp,
                    const float* __restrict__ alpha,
                    const float* __restrict__ beta,
                    const float* __restrict__ gamma,
                    float* __restrict__ out)
{
    __shared__ u64 tile[2][TILE_SZ];

    const int tid = threadIdx.x;
    const int tx  = tid & 7;         // column strip (4 output cols each)
    const int ty  = tid >> 3;        // output row within tile (0..15)

    const int b   = blockIdx.z >> 2;
    const int cg  = blockIdx.z & 3;
    const int c0  = cg * CH_PER_BLOCK;
    const int gx0 = blockIdx.x * TILE_W;
    const int gy0 = blockIdx.y * TILE_H;

    const int oy  = gy0 + ty;
    const int ocx = gx0 + tx * 4;

    // ---------------- per-pixel weights (shared across all channels) ----------
    const float al = alpha[0];
    const float be = beta[0];
    const float ga = gamma[0];

    u64 W2[4][4];                    // broadcast-packed normalized weights by tap distance
    {
        const float* prow = persp + ((size_t)b * HH * WW) + oy * WW + ocx;
        #pragma unroll
        for (int px = 0; px < 4; ++px) {
            float p  = prow[px];
            float z  = fmaf(be, p, ga);
            float sg = __fdividef(1.0f, 1.0f + __expf(-z));
            float sig = fmaxf(al * sg, 1e-4f);
            float u  = __fdividef(0.5f, sig * sig);
            float t1 = __expf(-u);
            float t4 = t1 * t1; t4 = t4 * t4;          // t^4
            float t9 = t4 * t4 * t1;                    // t^9
            float S  = 1.0f + 2.0f * (t1 + t4 + t9);
            float inv = __fdividef(1.0f, S);
            float w0 = inv, w1 = t1 * inv, w2 = t4 * inv, w3 = t9 * inv;
            W2[px][0] = pack2(w0, w0);
            W2[px][1] = pack2(w1, w1);
            W2[px][2] = pack2(w2, w2);
            W2[px][3] = pack2(w3, w3);
        }
    }

    const int sbase = ty * SROW + tx;
    const size_t plane = (size_t)HH * WW;
    const float* xbase = x + ((size_t)(b * CC + c0)) * plane;

    // Prologue: load + stage first channel pair (cold start, LDG exposed once).
    {
        float4 fa[2], fb[2];
        tile_ldg(xbase, gx0, gy0, tid, fa, fb);
        tile_sts(tile[0], tid, fa, fb);
    }
    __syncthreads();

    // ---------------- channel-pair loop (register-pipelined loads) -------------
    #pragma unroll 1
    for (int cp = 0; cp < CH_PER_BLOCK / 2; ++cp) {
        // Issue next tile's LDGs now; latency hidden by the compute below.
        float4 fa[2], fb[2];
        if (cp < CH_PER_BLOCK / 2 - 1) {
            tile_ldg(xbase + (size_t)(2 * cp + 2) * plane, gx0, gy0, tid, fa, fb);
        }

        const u64* cur = tile[cp & 1];

        // Vertical symmetry fold, then horizontal 7-tap, all packed f32x2.
        u64 acc[4];
        #pragma unroll
        for (int px = 0; px < 4; ++px) acc[px] = 0ull;

        #pragma unroll
        for (int d = 0; d < 4; ++d) {
            u64 g[10];
            if (d < 3) {
                const u64* ra = &cur[sbase + d * SROW];
                const u64* rb = &cur[sbase + (6 - d) * SROW];
                #pragma unroll
                for (int m = 0; m < 10; ++m) g[m] = add2(ra[m * 8], rb[m * 8]);
            } else {
                const u64* rc = &cur[sbase + 3 * SROW];
                #pragma unroll
                for (int m = 0; m < 10; ++m) g[m] = rc[m * 8];
            }
            const int vk = (d < 3) ? (3 - d) : 0;
            #pragma unroll
            for (int px = 0; px < 4; ++px) {
                u64 h = mul2(W2[px][3], g[px]);
                h = fma2(W2[px][2], g[px + 1], h);
                h = fma2(W2[px][1], g[px + 2], h);
                h = fma2(W2[px][0], g[px + 3], h);
                h = fma2(W2[px][1], g[px + 4], h);
                h = fma2(W2[px][2], g[px + 5], h);
                h = fma2(W2[px][3], g[px + 6], h);
                acc[px] = fma2(W2[px][vk], h, acc[px]);
            }
        }

        // Write out: channel c (.x lanes) and c+1 (.y lanes), one float4 each.
        float ax[4], ay[4];
        #pragma unroll
        for (int px = 0; px < 4; ++px) unpack2(acc[px], ax[px], ay[px]);

        const int c = c0 + 2 * cp;
        float* ob = out + ((size_t)(b * CC + c)) * plane + (oy << 8) + ocx;
        *reinterpret_cast<float4*>(ob)         = make_float4(ax[0], ax[1], ax[2], ax[3]);
        *reinterpret_cast<float4*>(ob + plane) = make_float4(ay[0], ay[1], ay[2], ay[3]);

        __syncthreads();   // all reads of tile[(cp+1)&1] (from iter cp-1) complete
        if (cp < CH_PER_BLOCK / 2 - 1) {
            tile_sts(tile[(cp + 1) & 1], tid, fa, fb);
        }
        __syncthreads();   // staged tile visible before next compute
    }
}

extern "C" void kernel_launch(void* const* d_in, const int* in_sizes, int n_in,
                              void* d_out, int out_size)
{
    const float* x     = (const float*)d_in[0];
    const float* persp = (const float*)d_in[1];
    const float* alpha = (const float*)d_in[2];
    const float* beta  = (const float*)d_in[3];
    const float* gamma = (const float*)d_in[4];
    float* out = (float*)d_out;

    dim3 grid(WW / TILE_W, HH / TILE_H, 4 * (CC / CH_PER_BLOCK)); // (8, 16, 16)
    dim3 block(NTHREADS);
    gauss_smooth_kernel<<<grid, block>>>(x, persp, alpha, beta, gamma, out);
}